// round 1
// baseline (speedup 1.0000x reference)
#include <cuda_runtime.h>
#include <math.h>

#define BATCH 64
#define TT 512
#define II 512
#define HH 512

#define NCTA 128
#define MB 16      // batches per CTA
#define NC 16      // columns per CTA
#define WS 516     // padded smem row stride (conflict-minimized, 16B-aligned rows)

// Persistent device state (allocation-free scratch)
__device__ float g_h[2][BATCH][HH];
__device__ unsigned int g_bar;

// ---------------------------------------------------------------------------
// init: zero h0 and the barrier counter (must be reset every launch/replay)
// ---------------------------------------------------------------------------
__global__ void init_kernel() {
    int tid = blockIdx.x * blockDim.x + threadIdx.x;
    if (tid == 0) g_bar = 0u;
    float* h0 = &g_h[0][0][0];
    for (int i = tid; i < BATCH * HH; i += gridDim.x * blockDim.x)
        h0[i] = 0.0f;
}

// ---------------------------------------------------------------------------
// Phase 1: xw[b,t,j] = sum_i x[b,t,i]*Wx[i,j] + bx[j] + bh[j]
// Viewed as SGEMM: M = B*T = 32768, N = 512, K = 512. Written into d_out mem
// region (overwritten in-place with h during phase 2 by the same thread).
// Tile: BM=128, BN=64, BK=16, 256 threads, 8x4 per thread.
// ---------------------------------------------------------------------------
#define BM 128
#define BN 64
#define BK 16
#define TM 8
#define TN 4

__global__ __launch_bounds__(256) void gemm_xw_kernel(
    const float* __restrict__ X,   // [32768, 512]
    const float* __restrict__ Wx,  // [512, 512]
    const float* __restrict__ bx,  // [512]
    const float* __restrict__ bh,  // [512]
    float* __restrict__ out)       // [32768, 512]
{
    __shared__ float As[BK][BM];       // transposed A tile
    __shared__ float Bs[BK][BN];

    const int tid = threadIdx.x;
    const int bm = blockIdx.y * BM;
    const int bn = blockIdx.x * BN;

    const int ty = tid >> 4;   // 0..15 -> 8 rows each
    const int tx = tid & 15;   // 0..15 -> 4 cols each

    float acc[TM][TN];
#pragma unroll
    for (int i = 0; i < TM; i++)
#pragma unroll
        for (int j = 0; j < TN; j++) acc[i][j] = 0.0f;

    const float* xg = X + (size_t)bm * II;
    const float* wg = Wx + bn;

    for (int k0 = 0; k0 < II; k0 += BK) {
        // Load A tile: 128 rows x 16 k, float4 along k. 512 float4 -> 2/thread.
#pragma unroll
        for (int i = 0; i < 2; i++) {
            int f4  = tid * 2 + i;
            int row = f4 >> 2;
            int kc  = (f4 & 3) * 4;
            float4 v = *(const float4*)(xg + (size_t)row * II + k0 + kc);
            As[kc + 0][row] = v.x;
            As[kc + 1][row] = v.y;
            As[kc + 2][row] = v.z;
            As[kc + 3][row] = v.w;
        }
        // Load B tile: 16 rows x 64 cols, 1 float4/thread.
        {
            int row = tid >> 4;
            int c4  = (tid & 15) * 4;
            float4 v = *(const float4*)(wg + (size_t)(k0 + row) * HH + c4);
            *(float4*)&Bs[row][c4] = v;
        }
        __syncthreads();

#pragma unroll
        for (int kk = 0; kk < BK; kk++) {
            float a[TM], b[TN];
#pragma unroll
            for (int i = 0; i < TM; i++) a[i] = As[kk][ty * TM + i];
#pragma unroll
            for (int j = 0; j < TN; j++) b[j] = Bs[kk][tx * TN + j];
#pragma unroll
            for (int i = 0; i < TM; i++)
#pragma unroll
                for (int j = 0; j < TN; j++) acc[i][j] += a[i] * b[j];
        }
        __syncthreads();
    }

#pragma unroll
    for (int i = 0; i < TM; i++) {
        int m = bm + ty * TM + i;
#pragma unroll
        for (int j = 0; j < TN; j++) {
            int n = bn + tx * TN + j;
            out[(size_t)m * HH + n] = acc[i][j] + bx[n] + bh[n];
        }
    }
}

// ---------------------------------------------------------------------------
// Phase 2: persistent recurrence.
// 128 CTAs (<=148 SMs -> all co-resident, custom grid barrier is safe).
// CTA = (batch group of 16) x (column group of 16). Wh column-slice lives in
// SMEM for the whole kernel, stored transposed [j][k] with padded stride.
// h ping-pongs in __device__ globals, read via __ldcg (L2, no stale L1).
// ---------------------------------------------------------------------------
__global__ __launch_bounds__(256, 1) void rnn_kernel(
    const float* __restrict__ Wh,  // [512, 512]  (k-major: Wh[k][j])
    float* __restrict__ out)       // mem [64,512,512] then hid [64,512]
{
    __shared__ float Whs[NC][WS];

    const int tid = threadIdx.x;
    const int jg = blockIdx.x & 31;   // 32 column groups
    const int bg = blockIdx.x >> 5;   // 4 batch groups
    const int j0 = jg * NC;
    const int b0 = bg * MB;

    // Load Wh slice transposed: Whs[j][k] = Wh[k][j0+j]
    for (int idx = tid; idx < NC * HH; idx += 256) {
        int j = idx & (NC - 1);
        int k = idx >> 4;
        Whs[j][k] = Wh[(size_t)k * HH + j0 + j];
    }
    __syncthreads();

    const int jl = tid & 15;
    const int bl = tid >> 4;
    const int b  = b0 + bl;
    const int j  = j0 + jl;

    float* mem = out;
    float* hid = out + (size_t)BATCH * TT * HH;

    const float4* wr = (const float4*)&Whs[jl][0];   // row stride 516*4 bytes, 16B aligned

    for (int t = 0; t < TT; t++) {
        const float* hcur = &g_h[t & 1][0][0];
        const float4* hb  = (const float4*)(hcur + b * HH);

        float acc = mem[((size_t)b * TT + t) * HH + j];

#pragma unroll 8
        for (int k4 = 0; k4 < HH / 4; k4++) {
            float4 hv = __ldcg(&hb[k4]);
            float4 wv = wr[k4];
            acc += hv.x * wv.x;
            acc += hv.y * wv.y;
            acc += hv.z * wv.z;
            acc += hv.w * wv.w;
        }

        float val = tanhf(acc);
        mem[((size_t)b * TT + t) * HH + j] = val;
        g_h[(t + 1) & 1][b][j] = val;
        if (t == TT - 1) hid[(size_t)b * HH + j] = val;

        // Grid-wide barrier: monotonically increasing counter, one arrive per CTA.
        __threadfence();
        __syncthreads();
        if (tid == 0) {
            atomicAdd(&g_bar, 1u);
            unsigned int target = (unsigned int)(t + 1) * NCTA;
            while (*(volatile unsigned int*)&g_bar < target) { }
            __threadfence();
        }
        __syncthreads();
    }
}

// ---------------------------------------------------------------------------
extern "C" void kernel_launch(void* const* d_in, const int* in_sizes, int n_in,
                              void* d_out, int out_size) {
    const float* x  = (const float*)d_in[0];  // [64, 512, 512]
    const float* Wx = (const float*)d_in[1];  // [512, 512]
    const float* Wh = (const float*)d_in[2];  // [512, 512]
    const float* bx = (const float*)d_in[3];  // [1, 512]
    const float* bh = (const float*)d_in[4];  // [1, 512]
    float* out = (float*)d_out;

    init_kernel<<<32, 256>>>();

    dim3 ggrid(HH / BN, (BATCH * TT) / BM);   // (8, 256)
    gemm_xw_kernel<<<ggrid, 256>>>(x, Wx, bx, bh, out);

    rnn_kernel<<<NCTA, 256>>>(Wh, out);
}

// round 2
// speedup vs baseline: 2.0572x; 2.0572x over previous
#include <cuda_runtime.h>

#define BATCH 64
#define TT 512
#define II 512
#define HH 512
#define NCTA 128

typedef unsigned long long ull;

// ---- packed f32x2 helpers (sm_100+) ----
__device__ __forceinline__ ull pack2(float x, float y) {
    ull r; asm("mov.b64 %0, {%1, %2};" : "=l"(r) : "f"(x), "f"(y)); return r;
}
__device__ __forceinline__ void unpack2(ull v, float& x, float& y) {
    asm("mov.b64 {%0, %1}, %2;" : "=f"(x), "=f"(y) : "l"(v));
}
__device__ __forceinline__ ull ffma2(ull a, ull b, ull c) {
    ull d; asm("fma.rn.f32x2 %0, %1, %2, %3;" : "=l"(d) : "l"(a), "l"(b), "l"(c)); return d;
}
__device__ __forceinline__ ull fadd2(ull a, ull b) {
    ull d; asm("add.rn.f32x2 %0, %1, %2;" : "=l"(d) : "l"(a), "l"(b)); return d;
}

// ---- persistent device state (allocation-free) ----
__device__ float g_h[2][BATCH][HH];
__device__ unsigned int g_bar;     // zero-initialized; self-resets each launch

// ---------------------------------------------------------------------------
// Phase 1: xw = X @ Wx + bx + bh   (M=32768, N=512, K=512), written into the
// mem region of d_out. 128x128x8 tile, double-buffered smem, f32x2 FFMA.
// ---------------------------------------------------------------------------
__global__ __launch_bounds__(256, 2) void gemm_xw_kernel(
    const float* __restrict__ X, const float* __restrict__ Wx,
    const float* __restrict__ bx, const float* __restrict__ bh,
    float* __restrict__ out)
{
    __shared__ float As[2][8][128];
    __shared__ float Bs[2][8][128];

    const int tid = threadIdx.x;
    const int bm = blockIdx.y * 128;
    const int bn = blockIdx.x * 128;
    const int ty = tid >> 4;          // 0..15 -> 8 rows
    const int tx = tid & 15;          // 0..15 -> 8 cols

    const int arow = tid >> 1;        // 0..127
    const int akc  = (tid & 1) * 4;   // 0 or 4
    const int brow = tid >> 5;        // 0..7
    const int bcc  = (tid & 31) * 4;  // 0..124

    const float* Ag = X + (size_t)(bm + arow) * II + akc;
    const float* Bg = Wx + (size_t)brow * HH + bn + bcc;

    { // preload tile 0
        float4 av = *(const float4*)Ag;
        float4 bv = *(const float4*)Bg;
        As[0][akc+0][arow] = av.x;
        As[0][akc+1][arow] = av.y;
        As[0][akc+2][arow] = av.z;
        As[0][akc+3][arow] = av.w;
        *(float4*)&Bs[0][brow][bcc] = bv;
    }
    __syncthreads();

    ull acc[8][4];
#pragma unroll
    for (int i = 0; i < 8; i++)
#pragma unroll
        for (int j = 0; j < 4; j++) acc[i][j] = 0ull;

    const int NT = II / 8;   // 64
    for (int kt = 0; kt < NT; kt++) {
        const int cur = kt & 1;
        float4 av, bv;
        if (kt + 1 < NT) {
            av = *(const float4*)(Ag + (kt + 1) * 8);
            bv = *(const float4*)(Bg + (size_t)(kt + 1) * 8 * HH);
        }
#pragma unroll
        for (int kk = 0; kk < 8; kk++) {
            float4 a0 = *(const float4*)&As[cur][kk][ty * 8];
            float4 a1 = *(const float4*)&As[cur][kk][ty * 8 + 4];
            float4 b0 = *(const float4*)&Bs[cur][kk][tx * 8];
            float4 b1 = *(const float4*)&Bs[cur][kk][tx * 8 + 4];
            ull bp[4] = { pack2(b0.x,b0.y), pack2(b0.z,b0.w),
                          pack2(b1.x,b1.y), pack2(b1.z,b1.w) };
            float aa[8] = { a0.x,a0.y,a0.z,a0.w, a1.x,a1.y,a1.z,a1.w };
#pragma unroll
            for (int i = 0; i < 8; i++) {
                ull ap = pack2(aa[i], aa[i]);
#pragma unroll
                for (int j = 0; j < 4; j++) acc[i][j] = ffma2(ap, bp[j], acc[i][j]);
            }
        }
        if (kt + 1 < NT) {
            const int nxt = cur ^ 1;
            __syncthreads();
            As[nxt][akc+0][arow] = av.x;
            As[nxt][akc+1][arow] = av.y;
            As[nxt][akc+2][arow] = av.z;
            As[nxt][akc+3][arow] = av.w;
            *(float4*)&Bs[nxt][brow][bcc] = bv;
            __syncthreads();
        }
    }

    const int n0 = bn + tx * 8;
    float bias[8];
#pragma unroll
    for (int j = 0; j < 8; j++) bias[j] = bx[n0 + j] + bh[n0 + j];

#pragma unroll
    for (int i = 0; i < 8; i++) {
        const int m = bm + ty * 8 + i;
        float o[8];
#pragma unroll
        for (int j = 0; j < 4; j++) unpack2(acc[i][j], o[j*2], o[j*2+1]);
        float4 v0 = make_float4(o[0]+bias[0], o[1]+bias[1], o[2]+bias[2], o[3]+bias[3]);
        float4 v1 = make_float4(o[4]+bias[4], o[5]+bias[5], o[6]+bias[6], o[7]+bias[7]);
        *(float4*)&out[(size_t)m * HH + n0]     = v0;
        *(float4*)&out[(size_t)m * HH + n0 + 4] = v1;
    }
}

// ---------------------------------------------------------------------------
// Phase 2: persistent recurrence, 128 CTAs x 128 threads.
// CTA tile: 16 batches x 16 columns. Thread (kg, jq, bq):
//   kg = k-chunk of 32 (16 chunks), jq = 4-column quad, bq = 8-batch half.
// Wh slab lives in registers as f32x2 pairs; h staged in SMEM (swizzled).
// k-partials folded across the 16 kg-lanes with a halving shfl tree.
// ---------------------------------------------------------------------------
#define FOLD_ROUND(M, N)                                            \
    _Pragma("unroll")                                               \
    for (int i = 0; i < (N); i++) {                                 \
        ull give = (kg & (M)) ? v[i] : v[i + (N)];                  \
        ull got  = __shfl_xor_sync(0xFFFFFFFFu, give, (M));         \
        ull keep = (kg & (M)) ? v[i + (N)] : v[i];                  \
        v[i] = fadd2(keep, got);                                    \
    }

__global__ __launch_bounds__(128, 1) void rnn_kernel(
    const float* __restrict__ Wh,   // [512, 512] k-major
    float* __restrict__ out)        // mem [64,512,512] then hid [64,512]
{
    __shared__ float4 h_s[16 * 128];   // 16 batches x 128 float4, XOR-swizzled

    const int tid = threadIdx.x;
    const int kg  = tid & 15;          // k-chunk id
    const int jq  = (tid >> 4) & 3;    // column quad
    const int bq  = tid >> 6;          // batch half
    const int jbase = (blockIdx.x & 31) * 16;
    const int bbase = (blockIdx.x >> 5) * 16;
    const int jcol0 = jbase + jq * 4;
    const int kgl = kg & 7;

    // Wh slab -> registers: w2[kl][jh] = (Wh[k][j0+2jh], Wh[k][j0+2jh+1])
    ull w2[32][2];
#pragma unroll
    for (int kl = 0; kl < 32; kl++) {
        float4 w = *(const float4*)&Wh[(size_t)(kg * 32 + kl) * HH + jcol0];
        w2[kl][0] = pack2(w.x, w.y);
        w2[kl][1] = pack2(w.z, w.w);
    }

    // After the fold, lane kg holds the sums for idx = bitrev4(kg):
    const int idx = ((kg & 1) << 3) | ((kg & 2) << 1) | ((kg & 4) >> 1) | ((kg & 8) >> 3);
    const int fb = bbase + bq * 8 + (idx >> 1);       // final batch row
    const int fj = jbase + jq * 4 + (idx & 1) * 2;    // final column pair

    float* mem = out;
    float* hid = out + (size_t)BATCH * TT * HH;

    for (int t = 0; t < TT; t++) {
        // prefetch xw for the final (fb, fj) pair
        float2 xw = *(const float2*)&mem[((size_t)fb * TT + t) * HH + fj];

        ull acc[8][2];
#pragma unroll
        for (int b = 0; b < 8; b++) { acc[b][0] = 0ull; acc[b][1] = 0ull; }

        if (t > 0) {
            // stage h (16 rows x 512 floats) L2 -> smem, swizzled
            const float4* gh = (const float4*)&g_h[t & 1][bbase][0];
#pragma unroll
            for (int i = 0; i < 16; i++) {
                int lin = tid + i * 128;
                int b = lin >> 7, c = lin & 127;
                h_s[(b << 7) + (c ^ ((c >> 3) & 7))] = __ldcg(gh + lin);
            }
            __syncthreads();

#pragma unroll
            for (int b = 0; b < 8; b++) {
                const float4* hrow = &h_s[((bq * 8 + b) << 7) + (kg << 3)];
#pragma unroll
                for (int i = 0; i < 8; i++) {
                    float4 hv = hrow[i ^ kgl];
                    ull hp;
                    hp = pack2(hv.x, hv.x);
                    acc[b][0] = ffma2(hp, w2[4*i+0][0], acc[b][0]);
                    acc[b][1] = ffma2(hp, w2[4*i+0][1], acc[b][1]);
                    hp = pack2(hv.y, hv.y);
                    acc[b][0] = ffma2(hp, w2[4*i+1][0], acc[b][0]);
                    acc[b][1] = ffma2(hp, w2[4*i+1][1], acc[b][1]);
                    hp = pack2(hv.z, hv.z);
                    acc[b][0] = ffma2(hp, w2[4*i+2][0], acc[b][0]);
                    acc[b][1] = ffma2(hp, w2[4*i+2][1], acc[b][1]);
                    hp = pack2(hv.w, hv.w);
                    acc[b][0] = ffma2(hp, w2[4*i+3][0], acc[b][0]);
                    acc[b][1] = ffma2(hp, w2[4*i+3][1], acc[b][1]);
                }
            }
        }

        // fold 16 partial-vectors across the 16 kg lanes
        ull v[16];
#pragma unroll
        for (int b = 0; b < 8; b++) { v[b*2+0] = acc[b][0]; v[b*2+1] = acc[b][1]; }
        FOLD_ROUND(1, 8)
        FOLD_ROUND(2, 4)
        FOLD_ROUND(4, 2)
        FOLD_ROUND(8, 1)

        float s0, s1; unpack2(v[0], s0, s1);
        float r0 = tanhf(xw.x + s0);
        float r1 = tanhf(xw.y + s1);
        float2 val = make_float2(r0, r1);
        *(float2*)&mem[((size_t)fb * TT + t) * HH + fj] = val;
        *(float2*)&g_h[(t + 1) & 1][fb][fj] = val;
        if (t == TT - 1) *(float2*)&hid[(size_t)fb * HH + fj] = val;

        if (t < TT - 1) {
            // grid-wide barrier (monotonic counter)
            __threadfence();
            __syncthreads();
            if (tid == 0) {
                atomicAdd(&g_bar, 1u);
                const unsigned int target = (unsigned int)(t + 1) * NCTA;
                while (*(volatile unsigned int*)&g_bar < target) { }
                __threadfence();
            }
            __syncthreads();
        }
    }

    // self-reset barrier counter for the next launch / graph replay
    __syncthreads();
    if (tid == 0) {
        unsigned int old = atomicAdd(&g_bar, 1u);
        if (old == (unsigned int)(TT - 1) * NCTA + (NCTA - 1)) {
            atomicExch(&g_bar, 0u);
        }
    }
}

// ---------------------------------------------------------------------------
extern "C" void kernel_launch(void* const* d_in, const int* in_sizes, int n_in,
                              void* d_out, int out_size) {
    const float* x  = (const float*)d_in[0];  // [64, 512, 512]
    const float* Wx = (const float*)d_in[1];  // [512, 512]
    const float* Wh = (const float*)d_in[2];  // [512, 512]
    const float* bx = (const float*)d_in[3];  // [1, 512]
    const float* bh = (const float*)d_in[4];  // [1, 512]
    float* out = (float*)d_out;

    dim3 ggrid(HH / 128, (BATCH * TT) / 128);   // (4, 256)
    gemm_xw_kernel<<<ggrid, 256>>>(x, Wx, bx, bh, out);

    rnn_kernel<<<NCTA, 128>>>(Wh, out);
}